// round 3
// baseline (speedup 1.0000x reference)
#include <cuda_runtime.h>

#define E_DIM 128
#define NPG   32
#define NHEAD 8
#define HD    16
#define NG    4             // graphs per CTA
#define ROWS  (NG * NPG)    // 128
#define TPB   512
#define PAD   132           // row stride (floats) for QA/Kh/Vh and Wt
#define KC    16            // k-chunk depth

typedef unsigned long long ull;

struct Smem {
    float  QA[ROWS * PAD];  // Q (row-major [r][c]); later AttT (transposed [c][r])
    float  Kh[ROWS * PAD];
    float  Vh[ROWS * PAD];
    float  Wt[KC * PAD];    // Wt[kk][col] = W[col][e0+kk]
    float2 Xd[KC * ROWS];   // duplicated a-operand: Xd[kk][row] = {x, x}
};

__device__ __forceinline__ ull pack2(float lo, float hi) {
    ull r; asm("mov.b64 %0, {%1, %2};" : "=l"(r) : "f"(lo), "f"(hi)); return r;
}
__device__ __forceinline__ void unpack2(ull p, float& lo, float& hi) {
    asm("mov.b64 {%0, %1}, %2;" : "=f"(lo), "=f"(hi) : "l"(p));
}
__device__ __forceinline__ void ffma2(ull& d, ull a, ull b) {
    asm("fma.rn.f32x2 %0, %1, %2, %0;" : "+l"(d) : "l"(a), "l"(b));
}

// 128x128 output tile, K=128: out[r][c] = (sum_k X[r][k]*W[c][k] + bias[c]) * scale
// FROM_GMEM: X rows come from gmem gx (row stride E_DIM), staged dup-transposed.
// else:      X is the attention output already living transposed in s.QA ([k][row]).
template<bool FROM_GMEM>
__device__ __forceinline__ void gemm128(
    Smem& s, const float* __restrict__ gx,
    const float* __restrict__ W, const float* __restrict__ bias,
    float scale, float* __restrict__ outp, int ostride, int tid)
{
    const int ty = tid >> 4;          // 0..31 -> rows [ty*4, ty*4+4)
    const int tx = tid & 15;          // 0..15 -> col-pairs {tx*2 + 32*cp}
    const int col  = tid >> 2;        // 0..127 staging index
    const int quad = (tid & 3) * 4;   // 0,4,8,12

    ull acc[4][4];
#pragma unroll
    for (int r = 0; r < 4; r++)
#pragma unroll
        for (int c = 0; c < 4; c++) acc[r][c] = 0ULL;

    // prefetch chunk 0
    float4 wp = *reinterpret_cast<const float4*>(W + col * E_DIM + quad);
    float4 xp;
    if (FROM_GMEM) xp = *reinterpret_cast<const float4*>(gx + col * E_DIM + quad);

#pragma unroll
    for (int c8 = 0; c8 < 8; c8++) {
        __syncthreads();   // previous chunk compute (or prior phase) done
        float xv0, xv1, xv2, xv3;
        if (FROM_GMEM) { xv0 = xp.x; xv1 = xp.y; xv2 = xp.z; xv3 = xp.w; }
        else {
            const int e0 = c8 * KC + quad;
            xv0 = s.QA[(e0 + 0) * PAD + col];
            xv1 = s.QA[(e0 + 1) * PAD + col];
            xv2 = s.QA[(e0 + 2) * PAD + col];
            xv3 = s.QA[(e0 + 3) * PAD + col];
        }
        s.Wt[(quad + 0) * PAD + col] = wp.x;
        s.Wt[(quad + 1) * PAD + col] = wp.y;
        s.Wt[(quad + 2) * PAD + col] = wp.z;
        s.Wt[(quad + 3) * PAD + col] = wp.w;
        s.Xd[(quad + 0) * ROWS + col] = make_float2(xv0, xv0);
        s.Xd[(quad + 1) * ROWS + col] = make_float2(xv1, xv1);
        s.Xd[(quad + 2) * ROWS + col] = make_float2(xv2, xv2);
        s.Xd[(quad + 3) * ROWS + col] = make_float2(xv3, xv3);
        __syncthreads();
        if (c8 < 7) {      // prefetch next chunk (overlaps compute)
            const int e0n = (c8 + 1) * KC;
            wp = *reinterpret_cast<const float4*>(W + col * E_DIM + e0n + quad);
            if (FROM_GMEM)
                xp = *reinterpret_cast<const float4*>(gx + col * E_DIM + e0n + quad);
        }
#pragma unroll
        for (int kk = 0; kk < KC; kk++) {
            const float2* xrow = s.Xd + kk * ROWS + ty * 4;
            const float*  wrow = s.Wt + kk * PAD + tx * 2;
            ull a0 = *reinterpret_cast<const ull*>(xrow + 0);
            ull a1 = *reinterpret_cast<const ull*>(xrow + 1);
            ull a2 = *reinterpret_cast<const ull*>(xrow + 2);
            ull a3 = *reinterpret_cast<const ull*>(xrow + 3);
            ull b0 = *reinterpret_cast<const ull*>(wrow);
            ull b1 = *reinterpret_cast<const ull*>(wrow + 32);
            ull b2 = *reinterpret_cast<const ull*>(wrow + 64);
            ull b3 = *reinterpret_cast<const ull*>(wrow + 96);
            ffma2(acc[0][0], a0, b0); ffma2(acc[0][1], a0, b1);
            ffma2(acc[0][2], a0, b2); ffma2(acc[0][3], a0, b3);
            ffma2(acc[1][0], a1, b0); ffma2(acc[1][1], a1, b1);
            ffma2(acc[1][2], a1, b2); ffma2(acc[1][3], a1, b3);
            ffma2(acc[2][0], a2, b0); ffma2(acc[2][1], a2, b1);
            ffma2(acc[2][2], a2, b2); ffma2(acc[2][3], a2, b3);
            ffma2(acc[3][0], a3, b0); ffma2(acc[3][1], a3, b1);
            ffma2(acc[3][2], a3, b2); ffma2(acc[3][3], a3, b3);
        }
    }

    // epilogue: unpack, add bias, scale, store
    float2 bs[4];
#pragma unroll
    for (int cp = 0; cp < 4; cp++)
        bs[cp] = *reinterpret_cast<const float2*>(bias + cp * 32 + tx * 2);
#pragma unroll
    for (int r = 0; r < 4; r++) {
        const int row = ty * 4 + r;
#pragma unroll
        for (int cp = 0; cp < 4; cp++) {
            float lo, hi; unpack2(acc[r][cp], lo, hi);
            float2 v;
            v.x = (lo + bs[cp].x) * scale;
            v.y = (hi + bs[cp].y) * scale;
            *reinterpret_cast<float2*>(outp + row * ostride + cp * 32 + tx * 2) = v;
        }
    }
}

extern "C" __global__ void __launch_bounds__(TPB, 1)
iattn_fused3_kernel(const float* __restrict__ query, const float* __restrict__ key,
                    const float* __restrict__ value,
                    const float* __restrict__ wq, const float* __restrict__ wk,
                    const float* __restrict__ wv,
                    const float* __restrict__ bq, const float* __restrict__ bk,
                    const float* __restrict__ bv,
                    const float* __restrict__ wo, const float* __restrict__ bo,
                    float* __restrict__ out)
{
    extern __shared__ char raw[];
    Smem& s = *reinterpret_cast<Smem*>(raw);
    const int tid = threadIdx.x;
    const size_t base = (size_t)blockIdx.x * ROWS * E_DIM;

    // QKV projections (q scale 1/sqrt(16)=0.25 applied to acc+bias, matching ref)
    gemm128<true>(s, query + base, wq, bq, 0.25f, s.QA, PAD, tid);
    gemm128<true>(s, key   + base, wk, bk, 1.0f,  s.Kh, PAD, tid);
    gemm128<true>(s, value + base, wv, bv, 1.0f,  s.Vh, PAD, tid);
    __syncthreads();   // QKV epilogue writes visible to attention

    // attention: 16 warps; warp w -> head h = w&7, graphs {2*(w>>3), 2*(w>>3)+1}
    {
        const int w  = tid >> 5;
        const int l  = tid & 31;
        const int h  = w & 7;
        const int gb = (w >> 3) * 2;
        const int c0 = h * HD;
        float oall[2][HD];
#pragma unroll
        for (int gi = 0; gi < 2; gi++) {
            const int g = gb + gi;
            const float* qr = s.QA + (g * NPG + l) * PAD + c0;
            ulonglong2 qa = *reinterpret_cast<const ulonglong2*>(qr);
            ulonglong2 qb = *reinterpret_cast<const ulonglong2*>(qr + 4);
            ulonglong2 qc = *reinterpret_cast<const ulonglong2*>(qr + 8);
            ulonglong2 qd = *reinterpret_cast<const ulonglong2*>(qr + 12);

            float sc[NPG];
            float mx = -1e30f;
#pragma unroll
            for (int j = 0; j < NPG; j++) {
                const float* kr = s.Kh + (g * NPG + j) * PAD + c0;
                ulonglong2 ka = *reinterpret_cast<const ulonglong2*>(kr);
                ulonglong2 kb = *reinterpret_cast<const ulonglong2*>(kr + 4);
                ulonglong2 kc = *reinterpret_cast<const ulonglong2*>(kr + 8);
                ulonglong2 kd = *reinterpret_cast<const ulonglong2*>(kr + 12);
                ull t2 = 0ULL;
                ffma2(t2, qa.x, ka.x); ffma2(t2, qa.y, ka.y);
                ffma2(t2, qb.x, kb.x); ffma2(t2, qb.y, kb.y);
                ffma2(t2, qc.x, kc.x); ffma2(t2, qc.y, kc.y);
                ffma2(t2, qd.x, kd.x); ffma2(t2, qd.y, kd.y);
                float tl, th; unpack2(t2, tl, th);
                const float t = tl + th;
                sc[j] = t;
                mx = fmaxf(mx, t);
            }
            float sum = 0.f;
#pragma unroll
            for (int j = 0; j < NPG; j++) { sc[j] = __expf(sc[j] - mx); sum += sc[j]; }
            const float inv = 1.0f / sum;

            ull o2[8];
#pragma unroll
            for (int i = 0; i < 8; i++) o2[i] = 0ULL;
#pragma unroll
            for (int j = 0; j < NPG; j++) {
                const ull p2 = pack2(sc[j], sc[j]);
                const float* vr = s.Vh + (g * NPG + j) * PAD + c0;
                ulonglong2 va = *reinterpret_cast<const ulonglong2*>(vr);
                ulonglong2 vb = *reinterpret_cast<const ulonglong2*>(vr + 4);
                ulonglong2 vc = *reinterpret_cast<const ulonglong2*>(vr + 8);
                ulonglong2 vd = *reinterpret_cast<const ulonglong2*>(vr + 12);
                ffma2(o2[0], p2, va.x); ffma2(o2[1], p2, va.y);
                ffma2(o2[2], p2, vb.x); ffma2(o2[3], p2, vb.y);
                ffma2(o2[4], p2, vc.x); ffma2(o2[5], p2, vc.y);
                ffma2(o2[6], p2, vd.x); ffma2(o2[7], p2, vd.y);
            }
#pragma unroll
            for (int i = 0; i < 8; i++) {
                float lo, hi; unpack2(o2[i], lo, hi);
                oall[gi][2 * i]     = lo * inv;
                oall[gi][2 * i + 1] = hi * inv;
            }
        }
        __syncthreads();   // all Q/K/V reads done before overlaying AttT on QA
#pragma unroll
        for (int gi = 0; gi < 2; gi++)
#pragma unroll
            for (int d = 0; d < HD; d++)
                s.QA[(c0 + d) * PAD + (gb + gi) * NPG + l] = oall[gi][d];
    }
    __syncthreads();   // AttT visible

    // out-projection; a-operand read chunk-wise from transposed AttT in s.QA
    gemm128<false>(s, nullptr, wo, bo, 1.0f, out + base, E_DIM, tid);
}

extern "C" void kernel_launch(void* const* d_in, const int* in_sizes, int n_in,
                              void* d_out, int out_size)
{
    const float* query = (const float*)d_in[0];
    const float* key_  = (const float*)d_in[1];
    const float* value = (const float*)d_in[2];
    const float* wq    = (const float*)d_in[3];
    const float* wk    = (const float*)d_in[4];
    const float* wv    = (const float*)d_in[5];
    const float* bq    = (const float*)d_in[6];
    const float* bk    = (const float*)d_in[7];
    const float* bv    = (const float*)d_in[8];
    const float* wo    = (const float*)d_in[9];
    const float* bo    = (const float*)d_in[10];
    float* out = (float*)d_out;

    const int N = in_sizes[0] / E_DIM;   // total nodes
    const int G = N / NPG;               // graphs
    const int grid = G / NG;

    cudaFuncSetAttribute(iattn_fused3_kernel,
                         cudaFuncAttributeMaxDynamicSharedMemorySize,
                         (int)sizeof(Smem));
    iattn_fused3_kernel<<<grid, TPB, sizeof(Smem)>>>(
        query, key_, value, wq, wk, wv, bq, bk, bv, wo, bo, out);
}

// round 5
// speedup vs baseline: 1.7347x; 1.7347x over previous
#include <cuda_runtime.h>
#include <cuda_bf16.h>
#include <cstdint>

typedef unsigned long long ull;

#define E_DIM 128
#define NPG   32
#define TPB   512
#define PAD   132           // fp32 row stride (floats)
#define XS    136           // bf16 row stride (elements)
#define XSB   272           // bf16 row stride (bytes)
#define XHALF 17408         // bytes per 64-row bf16 tile (64*272)
#define WHALF 34816         // bytes per 128-row bf16 tile (128*272)
#define WB    69632         // bytes per weight (hi+lo)

// smem byte offsets
#define OFF_W    0          // 69632: current weight hi/lo
#define OFF_X    69632      // 34816: X hi/lo tiles; later V_s fp32 (33792)
#define OFF_C    104448     // 34816: Q_s fp32 (33792); later attn-out hi/lo tiles
#define OFF_D    139264     // 33792: K_s fp32
#define OFF_BIAS 173056     // 512 floats
#define SMEM_TOTAL 175104

__device__ __align__(1024) unsigned char g_wconv[4 * WB];

// ---------- helpers ----------
__device__ __forceinline__ uint32_t s2u(const void* p) {
    uint32_t a;
    asm("{ .reg .u64 t; cvta.to.shared.u64 t, %1; cvt.u32.u64 %0, t; }" : "=r"(a) : "l"(p));
    return a;
}
__device__ __forceinline__ ull pack2(float lo, float hi) {
    ull r; asm("mov.b64 %0, {%1, %2};" : "=l"(r) : "f"(lo), "f"(hi)); return r;
}
__device__ __forceinline__ void unpack2(ull p, float& lo, float& hi) {
    asm("mov.b64 {%0, %1}, %2;" : "=f"(lo), "=f"(hi) : "l"(p));
}
__device__ __forceinline__ void ffma2(ull& d, ull a, ull b) {
    asm("fma.rn.f32x2 %0, %1, %2, %0;" : "+l"(d) : "l"(a), "l"(b));
}
__device__ __forceinline__ ull pack4bf(__nv_bfloat16 a, __nv_bfloat16 b,
                                       __nv_bfloat16 c, __nv_bfloat16 d) {
    uint32_t lo = ((uint32_t)__bfloat16_as_ushort(b) << 16) | __bfloat16_as_ushort(a);
    uint32_t hi = ((uint32_t)__bfloat16_as_ushort(d) << 16) | __bfloat16_as_ushort(c);
    return ((ull)hi << 32) | lo;
}
__device__ __forceinline__ void split4(float4 x, ull& hiw, ull& low) {
    __nv_bfloat16 h0 = __float2bfloat16(x.x), h1 = __float2bfloat16(x.y),
                  h2 = __float2bfloat16(x.z), h3 = __float2bfloat16(x.w);
    __nv_bfloat16 l0 = __float2bfloat16(x.x - __bfloat162float(h0));
    __nv_bfloat16 l1 = __float2bfloat16(x.y - __bfloat162float(h1));
    __nv_bfloat16 l2 = __float2bfloat16(x.z - __bfloat162float(h2));
    __nv_bfloat16 l3 = __float2bfloat16(x.w - __bfloat162float(h3));
    hiw = pack4bf(h0, h1, h2, h3);
    low = pack4bf(l0, l1, l2, l3);
}
__device__ __forceinline__ void ldsm4(uint32_t& r0, uint32_t& r1, uint32_t& r2,
                                      uint32_t& r3, uint32_t a) {
    asm volatile("ldmatrix.sync.aligned.m8n8.x4.shared.b16 {%0,%1,%2,%3}, [%4];"
                 : "=r"(r0), "=r"(r1), "=r"(r2), "=r"(r3) : "r"(a));
}
__device__ __forceinline__ void ldsm2(uint32_t& r0, uint32_t& r1, uint32_t a) {
    asm volatile("ldmatrix.sync.aligned.m8n8.x2.shared.b16 {%0,%1}, [%2];"
                 : "=r"(r0), "=r"(r1) : "r"(a));
}
__device__ __forceinline__ void mma_bf16(float* c, uint32_t a0, uint32_t a1,
                                         uint32_t a2, uint32_t a3,
                                         uint32_t b0, uint32_t b1) {
    asm volatile(
        "mma.sync.aligned.m16n8k16.row.col.f32.bf16.bf16.f32 "
        "{%0,%1,%2,%3}, {%4,%5,%6,%7}, {%8,%9}, {%0,%1,%2,%3};"
        : "+f"(c[0]), "+f"(c[1]), "+f"(c[2]), "+f"(c[3])
        : "r"(a0), "r"(a1), "r"(a2), "r"(a3), "r"(b0), "r"(b1));
}

// ---------- building blocks ----------
// X (64x128 f32, gmem) -> hi/lo bf16 tiles at OFF_X
__device__ __forceinline__ void convert_X(const float* __restrict__ gx, char* raw, int tid) {
    const int row  = tid >> 3;           // 0..63
    const int colb = (tid & 7) * 16;     // 16 consecutive cols
#pragma unroll
    for (int i = 0; i < 4; i++) {
        const int col = colb + i * 4;
        float4 x = *reinterpret_cast<const float4*>(gx + row * E_DIM + col);
        ull hw, lw; split4(x, hw, lw);
        *(ull*)(raw + OFF_X + row * XSB + col * 2)          = hw;
        *(ull*)(raw + OFF_X + XHALF + row * XSB + col * 2)  = lw;
    }
}
__device__ __forceinline__ void copy_W(int wsel, char* raw, int tid) {
    const ull* s = reinterpret_cast<const ull*>(g_wconv + wsel * WB);
    ull* d = reinterpret_cast<ull*>(raw + OFF_W);
#pragma unroll
    for (int i = 0; i < 17; i++) d[i * TPB + tid] = s[i * TPB + tid];
}

// 64x128 output, K=128, 3-split bf16 MMA. A tiles at offA (hi; lo at +XHALF),
// W at OFF_W (hi; lo at +WHALF). acc[sub][4] per warp (warp tile 16x32).
__device__ __forceinline__ void gemm_compute(char* raw, int offA, float acc[4][4],
                                             int w, int l) {
    const int wm = w >> 2, wn = w & 3;
    const uint32_t sb = s2u(raw);
#pragma unroll
    for (int s = 0; s < 4; s++)
#pragma unroll
        for (int i = 0; i < 4; i++) acc[s][i] = 0.f;
    const uint32_t aBase = sb + offA + (wm * 16 + (l & 15)) * XSB + ((l >> 4) * 8) * 2;
    const uint32_t bBase = sb + OFF_W + (wn * 32 + (l & 7)) * XSB + (((l >> 3) & 1) * 8) * 2;
#pragma unroll
    for (int sp = 0; sp < 3; sp++) {
        const uint32_t aA = aBase + (sp == 2 ? XHALF : 0);
        const uint32_t aB = bBase + (sp == 1 ? WHALF : 0);
#pragma unroll
        for (int k8 = 0; k8 < 8; k8++) {
            uint32_t a0, a1, a2, a3;
            ldsm4(a0, a1, a2, a3, aA + k8 * 32);
#pragma unroll
            for (int sub = 0; sub < 4; sub++) {
                uint32_t b0, b1;
                ldsm2(b0, b1, aB + k8 * 32 + sub * 8 * XSB);
                mma_bf16(acc[sub], a0, a1, a2, a3, b0, b1);
            }
        }
    }
}
__device__ __forceinline__ void epilogue(const float acc[4][4], const float* bias,
                                         float scale, float* dst, int dstride,
                                         int w, int l) {
    const int wm = w >> 2, wn = w & 3;
    const int r0 = wm * 16 + (l >> 2);
#pragma unroll
    for (int sub = 0; sub < 4; sub++) {
        const int cb = wn * 32 + sub * 8 + (l & 3) * 2;
        float2 v;
        v.x = (acc[sub][0] + bias[cb]) * scale;
        v.y = (acc[sub][1] + bias[cb + 1]) * scale;
        *reinterpret_cast<float2*>(dst + r0 * dstride + cb) = v;
        v.x = (acc[sub][2] + bias[cb]) * scale;
        v.y = (acc[sub][3] + bias[cb + 1]) * scale;
        *reinterpret_cast<float2*>(dst + (r0 + 8) * dstride + cb) = v;
    }
}

// ---------- pre-kernel: weights f32 -> bf16 hi/lo tiles in g_wconv ----------
extern "C" __global__ void wconv_kernel(const float* __restrict__ wq,
                                        const float* __restrict__ wk,
                                        const float* __restrict__ wv,
                                        const float* __restrict__ wo) {
    const int idx = (blockIdx.x * blockDim.x + threadIdx.x) * 4;
    const int wsel = idx >> 14;
    const float* W = (wsel == 0) ? wq : (wsel == 1) ? wk : (wsel == 2) ? wv : wo;
    const int rem = idx & 16383;
    const int c = rem >> 7, k = rem & 127;
    float4 x = *reinterpret_cast<const float4*>(W + c * 128 + k);
    ull hw, lw; split4(x, hw, lw);
    *(ull*)(g_wconv + wsel * WB + c * XSB + k * 2)         = hw;
    *(ull*)(g_wconv + wsel * WB + WHALF + c * XSB + k * 2) = lw;
}

// ---------- main fused kernel ----------
extern "C" __global__ void __launch_bounds__(TPB, 1)
iattn_mma_kernel(const float* __restrict__ query, const float* __restrict__ key,
                 const float* __restrict__ value,
                 const float* __restrict__ bq, const float* __restrict__ bk,
                 const float* __restrict__ bv, const float* __restrict__ bo,
                 float* __restrict__ out)
{
    extern __shared__ char raw[];
    const int tid = threadIdx.x;
    const int w = tid >> 5, l = tid & 31;
    const size_t base = (size_t)blockIdx.x * 64 * E_DIM;
    float* bias_s = reinterpret_cast<float*>(raw + OFF_BIAS);
    {
        const float* bsrc = (tid < 128) ? bq : (tid < 256) ? bk : (tid < 384) ? bv : bo;
        bias_s[tid] = bsrc[tid & 127];
    }

    float acc[4][4];

    // --- Q projection -> Q_s (fp32, OFF_C) ---
    convert_X(query + base, raw, tid);
    copy_W(0, raw, tid);
    __syncthreads();
    gemm_compute(raw, OFF_X, acc, w, l);
    epilogue(acc, bias_s, 0.25f, reinterpret_cast<float*>(raw + OFF_C), PAD, w, l);
    __syncthreads();

    // --- K projection -> K_s (fp32, OFF_D) ---
    convert_X(key + base, raw, tid);
    copy_W(1, raw, tid);
    __syncthreads();
    gemm_compute(raw, OFF_X, acc, w, l);
    epilogue(acc, bias_s + 128, 1.0f, reinterpret_cast<float*>(raw + OFF_D), PAD, w, l);
    __syncthreads();

    // --- V projection -> V_s (fp32, overlays X region) ---
    convert_X(value + base, raw, tid);
    copy_W(2, raw, tid);
    __syncthreads();
    gemm_compute(raw, OFF_X, acc, w, l);
    __syncthreads();   // all ldmatrix reads of Xv/Wv done before overlay
    epilogue(acc, bias_s + 256, 1.0f, reinterpret_cast<float*>(raw + OFF_X), PAD, w, l);
    copy_W(3, raw, tid);   // Wo (W region dead after sync above)
    __syncthreads();       // V_s + Wo visible

    // --- attention: warp w -> graph g=w>>3, head h=w&7 ---
    {
        const float* Qs = reinterpret_cast<const float*>(raw + OFF_C);
        const float* Ks = reinterpret_cast<const float*>(raw + OFF_D);
        const float* Vs = reinterpret_cast<const float*>(raw + OFF_X);
        const int g = w >> 3;
        const int h = w & 7;
        const int c0 = h * 16;
        const int row = g * NPG + l;

        const float* qr = Qs + row * PAD + c0;
        ulonglong2 qa = *reinterpret_cast<const ulonglong2*>(qr);
        ulonglong2 qb = *reinterpret_cast<const ulonglong2*>(qr + 4);
        ulonglong2 qc = *reinterpret_cast<const ulonglong2*>(qr + 8);
        ulonglong2 qd = *reinterpret_cast<const ulonglong2*>(qr + 12);

        float sc[NPG];
        float mx = -1e30f;
#pragma unroll
        for (int j = 0; j < NPG; j++) {
            const float* kr = Ks + (g * NPG + j) * PAD + c0;
            ulonglong2 ka = *reinterpret_cast<const ulonglong2*>(kr);
            ulonglong2 kb = *reinterpret_cast<const ulonglong2*>(kr + 4);
            ulonglong2 kc = *reinterpret_cast<const ulonglong2*>(kr + 8);
            ulonglong2 kd = *reinterpret_cast<const ulonglong2*>(kr + 12);
            ull t2 = 0ULL;
            ffma2(t2, qa.x, ka.x); ffma2(t2, qa.y, ka.y);
            ffma2(t2, qb.x, kb.x); ffma2(t2, qb.y, kb.y);
            ffma2(t2, qc.x, kc.x); ffma2(t2, qc.y, kc.y);
            ffma2(t2, qd.x, kd.x); ffma2(t2, qd.y, kd.y);
            float tl, th; unpack2(t2, tl, th);
            const float t = tl + th;
            sc[j] = t;
            mx = fmaxf(mx, t);
        }
        float sum = 0.f;
#pragma unroll
        for (int j = 0; j < NPG; j++) { sc[j] = __expf(sc[j] - mx); sum += sc[j]; }
        const float inv = 1.0f / sum;

        __syncthreads();   // all warps done reading Q_s before overlaying OFF_C

        ull o2[8];
#pragma unroll
        for (int i = 0; i < 8; i++) o2[i] = 0ULL;
#pragma unroll
        for (int j = 0; j < NPG; j++) {
            const ull p2 = pack2(sc[j], sc[j]);
            const float* vr = Vs + (g * NPG + j) * PAD + c0;
            ulonglong2 va = *reinterpret_cast<const ulonglong2*>(vr);
            ulonglong2 vb = *reinterpret_cast<const ulonglong2*>(vr + 4);
            ulonglong2 vc = *reinterpret_cast<const ulonglong2*>(vr + 8);
            ulonglong2 vd = *reinterpret_cast<const ulonglong2*>(vr + 12);
            ffma2(o2[0], p2, va.x); ffma2(o2[1], p2, va.y);
            ffma2(o2[2], p2, vb.x); ffma2(o2[3], p2, vb.y);
            ffma2(o2[4], p2, vc.x); ffma2(o2[5], p2, vc.y);
            ffma2(o2[6], p2, vd.x); ffma2(o2[7], p2, vd.y);
        }
        // write attention output as bf16 hi/lo tiles into OFF_C
#pragma unroll
        for (int p = 0; p < 4; p++) {
            float x0, x1, x2, x3;
            unpack2(o2[2 * p],     x0, x1);
            unpack2(o2[2 * p + 1], x2, x3);
            float4 x = make_float4(x0 * inv, x1 * inv, x2 * inv, x3 * inv);
            ull hw, lw; split4(x, hw, lw);
            const int col = c0 + 4 * p;
            *(ull*)(raw + OFF_C + row * XSB + col * 2)         = hw;
            *(ull*)(raw + OFF_C + XHALF + row * XSB + col * 2) = lw;
        }
    }
    __syncthreads();   // attn-out tiles complete

    // --- out projection -> gmem ---
    gemm_compute(raw, OFF_C, acc, w, l);
    epilogue(acc, bias_s + 384, 1.0f, out + base, E_DIM, w, l);
}

extern "C" void kernel_launch(void* const* d_in, const int* in_sizes, int n_in,
                              void* d_out, int out_size)
{
    const float* query = (const float*)d_in[0];
    const float* key_  = (const float*)d_in[1];
    const float* value = (const float*)d_in[2];
    const float* wq    = (const float*)d_in[3];
    const float* wk    = (const float*)d_in[4];
    const float* wv    = (const float*)d_in[5];
    const float* bq    = (const float*)d_in[6];
    const float* bk    = (const float*)d_in[7];
    const float* bv    = (const float*)d_in[8];
    const float* wo    = (const float*)d_in[9];
    const float* bo    = (const float*)d_in[10];
    float* out = (float*)d_out;

    const int N = in_sizes[0] / E_DIM;   // total nodes
    const int grid = N / 64;             // 2 graphs per CTA

    wconv_kernel<<<64, 256>>>(wq, wk, wv, wo);

    cudaFuncSetAttribute(iattn_mma_kernel,
                         cudaFuncAttributeMaxDynamicSharedMemorySize, SMEM_TOTAL);
    iattn_mma_kernel<<<grid, TPB, SMEM_TOTAL>>>(
        query, key_, value, bq, bk, bv, bo, out);
}

// round 6
// speedup vs baseline: 1.8671x; 1.0763x over previous
#include <cuda_runtime.h>
#include <cuda_bf16.h>
#include <cstdint>

typedef unsigned long long ull;

#define E_DIM 128
#define NPG   32
#define TPB   512
#define PAD   132           // fp32 row stride (floats)
#define XSB   272           // bf16 row stride (bytes)
#define XHALF 17408         // bytes per 64-row bf16 tile (64*272)
#define WHALF 34816         // bytes per 128-row bf16 tile (128*272)
#define WB    69632         // bytes per weight (hi+lo)

// smem byte offsets
#define OFF_W    0          // 69632: current weight hi/lo
#define OFF_X    69632      // 34816: X hi/lo tiles; later V_s fp32 (33792)
#define OFF_C    104448     // 34816: Q_s fp32 (33792); later attn-out hi/lo tiles
#define OFF_D    139264     // 33792: K_s fp32
#define OFF_BIAS 173056     // 512 floats
#define SMEM_TOTAL 175104

__device__ __align__(1024) unsigned char g_wconv[4 * WB];

// ---------- helpers ----------
__device__ __forceinline__ uint32_t s2u(const void* p) {
    uint32_t a;
    asm("{ .reg .u64 t; cvta.to.shared.u64 t, %1; cvt.u32.u64 %0, t; }" : "=r"(a) : "l"(p));
    return a;
}
__device__ __forceinline__ ull pack2(float lo, float hi) {
    ull r; asm("mov.b64 %0, {%1, %2};" : "=l"(r) : "f"(lo), "f"(hi)); return r;
}
__device__ __forceinline__ void unpack2(ull p, float& lo, float& hi) {
    asm("mov.b64 {%0, %1}, %2;" : "=f"(lo), "=f"(hi) : "l"(p));
}
__device__ __forceinline__ void ffma2(ull& d, ull a, ull b) {
    asm("fma.rn.f32x2 %0, %1, %2, %0;" : "+l"(d) : "l"(a), "l"(b));
}
__device__ __forceinline__ ull pack4bf(__nv_bfloat16 a, __nv_bfloat16 b,
                                       __nv_bfloat16 c, __nv_bfloat16 d) {
    uint32_t lo = ((uint32_t)__bfloat16_as_ushort(b) << 16) | __bfloat16_as_ushort(a);
    uint32_t hi = ((uint32_t)__bfloat16_as_ushort(d) << 16) | __bfloat16_as_ushort(c);
    return ((ull)hi << 32) | lo;
}
__device__ __forceinline__ void split4(float4 x, ull& hiw, ull& low) {
    __nv_bfloat16 h0 = __float2bfloat16(x.x), h1 = __float2bfloat16(x.y),
                  h2 = __float2bfloat16(x.z), h3 = __float2bfloat16(x.w);
    __nv_bfloat16 l0 = __float2bfloat16(x.x - __bfloat162float(h0));
    __nv_bfloat16 l1 = __float2bfloat16(x.y - __bfloat162float(h1));
    __nv_bfloat16 l2 = __float2bfloat16(x.z - __bfloat162float(h2));
    __nv_bfloat16 l3 = __float2bfloat16(x.w - __bfloat162float(h3));
    hiw = pack4bf(h0, h1, h2, h3);
    low = pack4bf(l0, l1, l2, l3);
}
__device__ __forceinline__ void ldsm4(uint32_t& r0, uint32_t& r1, uint32_t& r2,
                                      uint32_t& r3, uint32_t a) {
    asm volatile("ldmatrix.sync.aligned.m8n8.x4.shared.b16 {%0,%1,%2,%3}, [%4];"
                 : "=r"(r0), "=r"(r1), "=r"(r2), "=r"(r3) : "r"(a));
}
__device__ __forceinline__ void mma_bf16(float* c, const uint32_t* a,
                                         uint32_t b0, uint32_t b1) {
    asm volatile(
        "mma.sync.aligned.m16n8k16.row.col.f32.bf16.bf16.f32 "
        "{%0,%1,%2,%3}, {%4,%5,%6,%7}, {%8,%9}, {%0,%1,%2,%3};"
        : "+f"(c[0]), "+f"(c[1]), "+f"(c[2]), "+f"(c[3])
        : "r"(a[0]), "r"(a[1]), "r"(a[2]), "r"(a[3]), "r"(b0), "r"(b1));
}
__device__ __forceinline__ void cp16(uint32_t smem, const void* g) {
    asm volatile("cp.async.ca.shared.global [%0], [%1], 16;" :: "r"(smem), "l"(g) : "memory");
}
#define CP_COMMIT() asm volatile("cp.async.commit_group;" ::: "memory")
#define CP_WAIT0()  asm volatile("cp.async.wait_group 0;" ::: "memory")

// ---------- building blocks ----------
// X (64x128 f32, gmem) -> hi/lo bf16 tiles at OFF_X
__device__ __forceinline__ void convert_X(const float* __restrict__ gx, char* raw, int tid) {
    const int row  = tid >> 3;           // 0..63
    const int colb = (tid & 7) * 16;     // 16 consecutive cols
#pragma unroll
    for (int i = 0; i < 4; i++) {
        const int col = colb + i * 4;
        float4 x = *reinterpret_cast<const float4*>(gx + row * E_DIM + col);
        ull hw, lw; split4(x, hw, lw);
        *(ull*)(raw + OFF_X + row * XSB + col * 2)          = hw;
        *(ull*)(raw + OFF_X + XHALF + row * XSB + col * 2)  = lw;
    }
}
// async weight copy: 4352 x 16B = 69632B
__device__ __forceinline__ void copy_W_async(int wsel, uint32_t sb, int tid) {
    const char* s = reinterpret_cast<const char*>(g_wconv) + wsel * WB;
    const uint32_t d = sb + OFF_W;
#pragma unroll
    for (int i = 0; i < 8; i++)
        cp16(d + (i * TPB + tid) * 16, s + (size_t)(i * TPB + tid) * 16);
    if (tid < 256)
        cp16(d + (4096 + tid) * 16, s + (size_t)(4096 + tid) * 16);
    CP_COMMIT();
}

// 64x128 output, K=128, 3-split bf16 MMA with full fragment reuse per k8 step.
// A tiles at offA (hi; lo at +XHALF), W at OFF_W (hi; lo at +WHALF).
// Warp tile 16x32: acc[sub][4], sub = 8-col group.
__device__ __forceinline__ void gemm_compute(char* raw, int offA, float acc[4][4],
                                             int w, int l) {
    const int wm = w >> 2, wn = w & 3;
    const uint32_t sb = s2u(raw);
#pragma unroll
    for (int s = 0; s < 4; s++)
#pragma unroll
        for (int i = 0; i < 4; i++) acc[s][i] = 0.f;
    // A: row = wm*16 + (l&15), k-col = (l>>4)*8
    const uint32_t aBase = sb + offA + (wm * 16 + (l & 15)) * XSB + (l >> 4) * 16;
    // B x4 covering 2 subs: row = wn*32 + (l&7) + ((l>>4)&1)*8, k-col = ((l>>3)&1)*8
    const uint32_t bBase = sb + OFF_W +
        (wn * 32 + (l & 7) + ((l >> 4) & 1) * 8) * XSB + ((l >> 3) & 1) * 16;
#pragma unroll
    for (int k8 = 0; k8 < 8; k8++) {
        uint32_t ah[4], al[4];
        ldsm4(ah[0], ah[1], ah[2], ah[3], aBase + k8 * 32);
        ldsm4(al[0], al[1], al[2], al[3], aBase + XHALF + k8 * 32);
        uint32_t bh[8], bl[8];
        ldsm4(bh[0], bh[1], bh[2], bh[3], bBase + k8 * 32);              // subs 0,1
        ldsm4(bh[4], bh[5], bh[6], bh[7], bBase + 16 * XSB + k8 * 32);   // subs 2,3
        ldsm4(bl[0], bl[1], bl[2], bl[3], bBase + WHALF + k8 * 32);
        ldsm4(bl[4], bl[5], bl[6], bl[7], bBase + WHALF + 16 * XSB + k8 * 32);
#pragma unroll
        for (int sub = 0; sub < 4; sub++) {
            mma_bf16(acc[sub], ah, bh[2 * sub], bh[2 * sub + 1]);  // hi*hi
            mma_bf16(acc[sub], ah, bl[2 * sub], bl[2 * sub + 1]);  // hi*lo
            mma_bf16(acc[sub], al, bh[2 * sub], bh[2 * sub + 1]);  // lo*hi
        }
    }
}
__device__ __forceinline__ void epilogue(const float acc[4][4], const float* bias,
                                         float scale, float* dst, int dstride,
                                         int w, int l) {
    const int wm = w >> 2, wn = w & 3;
    const int r0 = wm * 16 + (l >> 2);
#pragma unroll
    for (int sub = 0; sub < 4; sub++) {
        const int cb = wn * 32 + sub * 8 + (l & 3) * 2;
        float2 v;
        v.x = (acc[sub][0] + bias[cb]) * scale;
        v.y = (acc[sub][1] + bias[cb + 1]) * scale;
        *reinterpret_cast<float2*>(dst + r0 * dstride + cb) = v;
        v.x = (acc[sub][2] + bias[cb]) * scale;
        v.y = (acc[sub][3] + bias[cb + 1]) * scale;
        *reinterpret_cast<float2*>(dst + (r0 + 8) * dstride + cb) = v;
    }
}

// ---------- pre-kernel: weights f32 -> bf16 hi/lo tiles in g_wconv ----------
extern "C" __global__ void wconv_kernel(const float* __restrict__ wq,
                                        const float* __restrict__ wk,
                                        const float* __restrict__ wv,
                                        const float* __restrict__ wo) {
    const int idx = (blockIdx.x * blockDim.x + threadIdx.x) * 4;
    const int wsel = idx >> 14;
    const float* W = (wsel == 0) ? wq : (wsel == 1) ? wk : (wsel == 2) ? wv : wo;
    const int rem = idx & 16383;
    const int c = rem >> 7, k = rem & 127;
    float4 x = *reinterpret_cast<const float4*>(W + c * 128 + k);
    ull hw, lw; split4(x, hw, lw);
    *(ull*)(g_wconv + wsel * WB + c * XSB + k * 2)         = hw;
    *(ull*)(g_wconv + wsel * WB + WHALF + c * XSB + k * 2) = lw;
}

// ---------- main fused kernel ----------
extern "C" __global__ void __launch_bounds__(TPB, 1)
iattn_mma2_kernel(const float* __restrict__ query, const float* __restrict__ key,
                  const float* __restrict__ value,
                  const float* __restrict__ bq, const float* __restrict__ bk,
                  const float* __restrict__ bv, const float* __restrict__ bo,
                  float* __restrict__ out)
{
    extern __shared__ char raw[];
    const int tid = threadIdx.x;
    const int w = tid >> 5, l = tid & 31;
    const size_t base = (size_t)blockIdx.x * 64 * E_DIM;
    const uint32_t sb = s2u(raw);
    float* bias_s = reinterpret_cast<float*>(raw + OFF_BIAS);

    copy_W_async(0, sb, tid);          // Wq copy overlaps bias + convert
    {
        const float* bsrc = (tid < 128) ? bq : (tid < 256) ? bk : (tid < 384) ? bv : bo;
        bias_s[tid] = bsrc[tid & 127];
    }

    float acc[4][4];

    // --- Q projection -> Q_s (fp32, OFF_C) ---
    convert_X(query + base, raw, tid);
    CP_WAIT0();
    __syncthreads();
    gemm_compute(raw, OFF_X, acc, w, l);
    epilogue(acc, bias_s, 0.25f, reinterpret_cast<float*>(raw + OFF_C), PAD, w, l);
    __syncthreads();

    // --- K projection -> K_s (fp32, OFF_D) ---
    copy_W_async(1, sb, tid);
    convert_X(key + base, raw, tid);
    CP_WAIT0();
    __syncthreads();
    gemm_compute(raw, OFF_X, acc, w, l);
    epilogue(acc, bias_s + 128, 1.0f, reinterpret_cast<float*>(raw + OFF_D), PAD, w, l);
    __syncthreads();

    // --- V projection -> V_s (fp32, overlays X region) ---
    copy_W_async(2, sb, tid);
    convert_X(value + base, raw, tid);
    CP_WAIT0();
    __syncthreads();
    gemm_compute(raw, OFF_X, acc, w, l);
    __syncthreads();   // all ldmatrix reads of Xv/Wv done before overlay
    epilogue(acc, bias_s + 256, 1.0f, reinterpret_cast<float*>(raw + OFF_X), PAD, w, l);
    copy_W_async(3, sb, tid);   // Wo (W region dead after sync above)
    CP_WAIT0();
    __syncthreads();            // V_s + Wo visible

    // --- attention: warp w -> graph g=w>>3, head h=w&7 ---
    {
        const float* Qs = reinterpret_cast<const float*>(raw + OFF_C);
        const float* Ks = reinterpret_cast<const float*>(raw + OFF_D);
        const float* Vs = reinterpret_cast<const float*>(raw + OFF_X);
        const int g = w >> 3;
        const int h = w & 7;
        const int c0 = h * 16;
        const int row = g * NPG + l;

        const float* qr = Qs + row * PAD + c0;
        ulonglong2 qa = *reinterpret_cast<const ulonglong2*>(qr);
        ulonglong2 qb = *reinterpret_cast<const ulonglong2*>(qr + 4);
        ulonglong2 qc = *reinterpret_cast<const ulonglong2*>(qr + 8);
        ulonglong2 qd = *reinterpret_cast<const ulonglong2*>(qr + 12);

        float sc[NPG];
        float mx = -1e30f;
#pragma unroll
        for (int j = 0; j < NPG; j++) {
            const float* kr = Ks + (g * NPG + j) * PAD + c0;
            ulonglong2 ka = *reinterpret_cast<const ulonglong2*>(kr);
            ulonglong2 kb = *reinterpret_cast<const ulonglong2*>(kr + 4);
            ulonglong2 kc = *reinterpret_cast<const ulonglong2*>(kr + 8);
            ulonglong2 kd = *reinterpret_cast<const ulonglong2*>(kr + 12);
            ull t2 = 0ULL;
            ffma2(t2, qa.x, ka.x); ffma2(t2, qa.y, ka.y);
            ffma2(t2, qb.x, kb.x); ffma2(t2, qb.y, kb.y);
            ffma2(t2, qc.x, kc.x); ffma2(t2, qc.y, kc.y);
            ffma2(t2, qd.x, kd.x); ffma2(t2, qd.y, kd.y);
            float tl, th; unpack2(t2, tl, th);
            const float t = tl + th;
            sc[j] = t;
            mx = fmaxf(mx, t);
        }
        float sum = 0.f;
#pragma unroll
        for (int j = 0; j < NPG; j++) { sc[j] = __expf(sc[j] - mx); sum += sc[j]; }
        const float inv = 1.0f / sum;

        __syncthreads();   // all warps done reading Q_s before overlaying OFF_C

        ull o2[8];
#pragma unroll
        for (int i = 0; i < 8; i++) o2[i] = 0ULL;
#pragma unroll
        for (int j = 0; j < NPG; j++) {
            const ull p2 = pack2(sc[j], sc[j]);
            const float* vr = Vs + (g * NPG + j) * PAD + c0;
            ulonglong2 va = *reinterpret_cast<const ulonglong2*>(vr);
            ulonglong2 vb = *reinterpret_cast<const ulonglong2*>(vr + 4);
            ulonglong2 vc = *reinterpret_cast<const ulonglong2*>(vr + 8);
            ulonglong2 vd = *reinterpret_cast<const ulonglong2*>(vr + 12);
            ffma2(o2[0], p2, va.x); ffma2(o2[1], p2, va.y);
            ffma2(o2[2], p2, vb.x); ffma2(o2[3], p2, vb.y);
            ffma2(o2[4], p2, vc.x); ffma2(o2[5], p2, vc.y);
            ffma2(o2[6], p2, vd.x); ffma2(o2[7], p2, vd.y);
        }
        // write attention output as bf16 hi/lo tiles into OFF_C
#pragma unroll
        for (int p = 0; p < 4; p++) {
            float x0, x1, x2, x3;
            unpack2(o2[2 * p],     x0, x1);
            unpack2(o2[2 * p + 1], x2, x3);
            float4 x = make_float4(x0 * inv, x1 * inv, x2 * inv, x3 * inv);
            ull hw, lw; split4(x, hw, lw);
            const int col = c0 + 4 * p;
            *(ull*)(raw + OFF_C + row * XSB + col * 2)         = hw;
            *(ull*)(raw + OFF_C + XHALF + row * XSB + col * 2) = lw;
        }
    }
    __syncthreads();   // attn-out tiles complete

    // --- out projection -> gmem ---
    gemm_compute(raw, OFF_C, acc, w, l);
    epilogue(acc, bias_s + 384, 1.0f, out + base, E_DIM, w, l);
}

extern "C" void kernel_launch(void* const* d_in, const int* in_sizes, int n_in,
                              void* d_out, int out_size)
{
    const float* query = (const float*)d_in[0];
    const float* key_  = (const float*)d_in[1];
    const float* value = (const float*)d_in[2];
    const float* wq    = (const float*)d_in[3];
    const float* wk    = (const float*)d_in[4];
    const float* wv    = (const float*)d_in[5];
    const float* bq    = (const float*)d_in[6];
    const float* bk    = (const float*)d_in[7];
    const float* bv    = (const float*)d_in[8];
    const float* wo    = (const float*)d_in[9];
    const float* bo    = (const float*)d_in[10];
    float* out = (float*)d_out;

    const int N = in_sizes[0] / E_DIM;   // total nodes
    const int grid = N / 64;             // 2 graphs per CTA

    wconv_kernel<<<64, 256>>>(wq, wk, wv, wo);

    cudaFuncSetAttribute(iattn_mma2_kernel,
                         cudaFuncAttributeMaxDynamicSharedMemorySize, SMEM_TOTAL);
    iattn_mma2_kernel<<<grid, TPB, SMEM_TOTAL>>>(
        query, key_, value, bq, bk, bv, bo, out);
}